// round 6
// baseline (speedup 1.0000x reference)
#include <cuda_runtime.h>

#define NB 16
#define TQ 256
#define TK 256
#define DD 256
#define FF 36
#define HH 8
#define DK 32
#define SFD 6

// Scratch (allocation-free rule: __device__ globals)
__device__ float g_Q[NB*TQ*DD];        // [b][q][h*DK+j]
__device__ float g_K[NB*TK*DD];        // [b][k][h*DK+j]
__device__ float g_HN[NB*TQ*FF*HH];    // [b][q][f][h]

// ---------------------------------------------------------------------------
// Packed fp32x2 helpers (sm_103a: FFMA2 via PTX only)
// ---------------------------------------------------------------------------
__device__ __forceinline__ float2 fma2(float2 a, float2 b, float2 c) {
    float2 d;
    asm("fma.rn.f32x2 %0, %1, %2, %3;"
        : "=l"(reinterpret_cast<unsigned long long&>(d))
        : "l"(reinterpret_cast<unsigned long long&>(a)),
          "l"(reinterpret_cast<unsigned long long&>(b)),
          "l"(reinterpret_cast<unsigned long long&>(c)));
    return d;
}
__device__ __forceinline__ float2 dup2(float s) { return make_float2(s, s); }
__device__ __forceinline__ float2 tanh2(float2 a) {
    float2 r;
    asm("tanh.approx.f32 %0, %1;" : "=f"(r.x) : "f"(a.x));
    asm("tanh.approx.f32 %0, %1;" : "=f"(r.y) : "f"(a.y));
    return r;
}

// ---------------------------------------------------------------------------
// Kernel 1: head projections, 16 rows/block, row-pairs packed into FFMA2.
// W loads software-pipelined (double-buffered 8-deep) to hide L2 latency.
// ---------------------------------------------------------------------------
__global__ void __launch_bounds__(256) proj_kernel(
        const float* __restrict__ query, const float* __restrict__ key,
        const float* __restrict__ Wq,    const float* __restrict__ Wk) {
    __shared__ __align__(16) float xst[DD][20];
    int n0 = blockIdx.x * 16;
    int which = blockIdx.y;
    const float* x = which ? key : query;
    const float* W = which ? Wk : Wq;
    int t = threadIdx.x;

#pragma unroll
    for (int r = 0; r < 16; ++r)
        xst[t][r] = x[(size_t)(n0 + r)*DD + t];
    __syncthreads();

    int h = t >> 5, j = t & 31;
    const float* w = W + h*DD*DK + j;

    float2 acc[8];
#pragma unroll
    for (int r = 0; r < 8; ++r) acc[r] = make_float2(0.f, 0.f);

    float wbuf[8];
#pragma unroll
    for (int p = 0; p < 8; ++p) wbuf[p] = w[p*DK];

#pragma unroll 1
    for (int c = 0; c < 32; ++c) {       // chunks of 8 d
        float wcur[8];
#pragma unroll
        for (int p = 0; p < 8; ++p) wcur[p] = wbuf[p];
        if (c < 31) {
#pragma unroll
            for (int p = 0; p < 8; ++p)
                wbuf[p] = w[((c+1)*8 + p)*DK];   // prefetch next chunk
        }
#pragma unroll
        for (int p = 0; p < 8; ++p) {
            int d = c*8 + p;
            float2 wv = dup2(wcur[p]);
            const float4* xr = (const float4*)&xst[d][0];
            float4 a = xr[0], b = xr[1], cc = xr[2], e = xr[3];
            acc[0] = fma2(wv, *(const float2*)&a.x,  acc[0]);
            acc[1] = fma2(wv, *(const float2*)&a.z,  acc[1]);
            acc[2] = fma2(wv, *(const float2*)&b.x,  acc[2]);
            acc[3] = fma2(wv, *(const float2*)&b.z,  acc[3]);
            acc[4] = fma2(wv, *(const float2*)&cc.x, acc[4]);
            acc[5] = fma2(wv, *(const float2*)&cc.z, acc[5]);
            acc[6] = fma2(wv, *(const float2*)&e.x,  acc[6]);
            acc[7] = fma2(wv, *(const float2*)&e.z,  acc[7]);
        }
    }

    float* out = which ? g_K : g_Q;
#pragma unroll
    for (int r = 0; r < 8; ++r) {
        out[(size_t)(n0 + 2*r    )*DD + t] = acc[r].x;
        out[(size_t)(n0 + 2*r + 1)*DD + t] = acc[r].y;
    }
}

// ---------------------------------------------------------------------------
// Kernel 2 (fused score+apply): per (b, h, qtile-64) block, loop k-tiles of 32.
// Phase A: E[kk][q] = exp(Q.K) into smem. Phase B: accumulate num/den.
// Register-lean: K staged in 8-wide chunks, no operand temp arrays.
// ---------------------------------------------------------------------------
__global__ void __launch_bounds__(128, 4) fused_attn_kernel(
        const float* __restrict__ value, const float* __restrict__ mask) {
    int b = blockIdx.x, h = blockIdx.y;
    int q0 = blockIdx.z * 64;
    int t = threadIdx.x;

    __shared__ __align__(16) float Qst[32][68];     // [j][q] transposed Q tile
    __shared__ __align__(16) float Ksd[32][66];     // [kk][2j] duplicated K tile
    __shared__ __align__(16) float Es[32][68];      // [kk][q]
    __shared__ __align__(16) float Cs[32][4][20];   // [kk][fg][(mv,m)x9 + pad]

    // Load Q tile transposed (once per block)
    for (int i = t; i < 64*32; i += 128) {
        int q = i >> 5, j = i & 31;
        Qst[j][q] = g_Q[(size_t)(b*TQ + q0 + q)*DD + h*DK + j];
    }

    // Phase B mapping
    int qg = t >> 2;            // q local = qg*2 + qq
    int fg = t & 3;             // f = fg*9 + i
    // Phase A mapping
    int kkA = t & 31;
    int qq4 = t >> 5;           // 16-q chunk

    float2 nd[2][9];
#pragma unroll
    for (int qq = 0; qq < 2; ++qq)
#pragma unroll
        for (int i = 0; i < 9; ++i) nd[qq][i] = make_float2(0.f, 0.f);

#pragma unroll 1
    for (int kt = 0; kt < TK; kt += 32) {
        __syncthreads();   // previous iteration's readers of Ksd/Cs done
        // K tile fill, duplicated for FFMA2: 32kk x 32j, 8 per thread
#pragma unroll
        for (int r = 0; r < 8; ++r) {
            int i = t + r*128;
            int kk = i >> 5, j = i & 31;
            float kv = g_K[(size_t)(b*TK + kt + kk)*DD + h*DK + j];
            *(float2*)&Ksd[kk][2*j] = make_float2(kv, kv);
        }
        // Cs fill: 32k x 9 float4-groups over f
        for (int i = t; i < 288; i += 128) {
            int k = i / 9;
            int c4 = (i - k*9) * 4;
            size_t base = (size_t)(b*TK + kt + k)*FF + c4;
            float4 mm = *(const float4*)(mask + base);
            float4 vv = *(const float4*)(value + base);
#pragma unroll
            for (int u = 0; u < 4; ++u) {
                int f = c4 + u;
                int g = f / 9, ii = f - g*9;
                float m = (&mm.x)[u], v = (&vv.x)[u];
                Cs[k][g][2*ii]   = m * v;
                Cs[k][g][2*ii+1] = m;
            }
        }
        __syncthreads();

        // ---- Phase A: thread owns kk = kkA, computes 16 q's (qq4*16..+15)
        {
            float2 acc2[8];
#pragma unroll
            for (int p = 0; p < 8; ++p) acc2[p] = make_float2(0.f, 0.f);
#pragma unroll
            for (int jc = 0; jc < 4; ++jc) {      // 8 j at a time (reg-lean)
                float2 kr2[8];
#pragma unroll
                for (int j = 0; j < 8; ++j)
                    kr2[j] = *(const float2*)&Ksd[kkA][2*(jc*8 + j)];
#pragma unroll
                for (int j = 0; j < 8; ++j) {
                    const float4* qp = (const float4*)&Qst[jc*8 + j][qq4*16];
#pragma unroll
                    for (int c = 0; c < 4; ++c) {
                        float4 qv = qp[c];
                        acc2[2*c]   = fma2(*(const float2*)&qv.x, kr2[j], acc2[2*c]);
                        acc2[2*c+1] = fma2(*(const float2*)&qv.z, kr2[j], acc2[2*c+1]);
                    }
                }
            }
#pragma unroll
            for (int c = 0; c < 4; ++c) {
                float4 ev;
                ev.x = __expf(fminf(acc2[2*c].x,   80.f));
                ev.y = __expf(fminf(acc2[2*c].y,   80.f));
                ev.z = __expf(fminf(acc2[2*c+1].x, 80.f));
                ev.w = __expf(fminf(acc2[2*c+1].y, 80.f));
                *(float4*)&Es[kkA][qq4*16 + 4*c] = ev;
            }
        }
        __syncthreads();

        // ---- Phase B: accumulate num/den (no temp arrays)
#pragma unroll 4
        for (int kk = 0; kk < 32; ++kk) {
            float2 e2 = *(const float2*)&Es[kk][qg*2];
            float2 e0 = dup2(e2.x), e1 = dup2(e2.y);
            const float4* cp = (const float4*)&Cs[kk][fg][0];
            float4 c0 = cp[0], c1 = cp[1], c2 = cp[2], c3 = cp[3], c4v = cp[4];
            nd[0][0] = fma2(e0, *(const float2*)&c0.x,  nd[0][0]);
            nd[1][0] = fma2(e1, *(const float2*)&c0.x,  nd[1][0]);
            nd[0][1] = fma2(e0, *(const float2*)&c0.z,  nd[0][1]);
            nd[1][1] = fma2(e1, *(const float2*)&c0.z,  nd[1][1]);
            nd[0][2] = fma2(e0, *(const float2*)&c1.x,  nd[0][2]);
            nd[1][2] = fma2(e1, *(const float2*)&c1.x,  nd[1][2]);
            nd[0][3] = fma2(e0, *(const float2*)&c1.z,  nd[0][3]);
            nd[1][3] = fma2(e1, *(const float2*)&c1.z,  nd[1][3]);
            nd[0][4] = fma2(e0, *(const float2*)&c2.x,  nd[0][4]);
            nd[1][4] = fma2(e1, *(const float2*)&c2.x,  nd[1][4]);
            nd[0][5] = fma2(e0, *(const float2*)&c2.z,  nd[0][5]);
            nd[1][5] = fma2(e1, *(const float2*)&c2.z,  nd[1][5]);
            nd[0][6] = fma2(e0, *(const float2*)&c3.x,  nd[0][6]);
            nd[1][6] = fma2(e1, *(const float2*)&c3.x,  nd[1][6]);
            nd[0][7] = fma2(e0, *(const float2*)&c3.z,  nd[0][7]);
            nd[1][7] = fma2(e1, *(const float2*)&c3.z,  nd[1][7]);
            nd[0][8] = fma2(e0, *(const float2*)&c4v.x, nd[0][8]);
            nd[1][8] = fma2(e1, *(const float2*)&c4v.x, nd[1][8]);
        }
    }

#pragma unroll
    for (int qq = 0; qq < 2; ++qq) {
        int q = q0 + qg*2 + qq;
        float* o = g_HN + (size_t)(b*TQ + q)*FF*HH + h;
#pragma unroll
        for (int i = 0; i < 9; ++i) {
            int f = fg*9 + i;
            o[(size_t)f*HH] = __fdividef(nd[qq][i].x, nd[qq][i].y);
        }
    }
}

// ---------------------------------------------------------------------------
// Kernel 3: fused epilogue. Block = 2 (b,q) rows; 64 threads per row; thread
// owns 4 d's = two FFMA2 pairs.
// ---------------------------------------------------------------------------
__global__ void __launch_bounds__(128) epilogue_kernel(
        const float* __restrict__ Wc,  const float* __restrict__ bc,
        const float* __restrict__ Wo1, const float* __restrict__ bo1,
        const float* __restrict__ Wo2, const float* __restrict__ bo2,
        float* __restrict__ out) {
    int t    = threadIdx.x;
    int half = t >> 6;           // which bq of the pair
    int u    = t & 63;           // d base
    int bq   = 2*blockIdx.x + half;

    __shared__ __align__(16) float2 hs2[2][FF*HH];   // duplicated pairs, per bq
    __shared__ __align__(16) float2 w12[FF*SFD];

    const float* hn0 = g_HN + (size_t)(2*blockIdx.x)*FF*HH;
    for (int i = t; i < 144; i += 128) {        // 2 x 72 float4
        int which = i / 72, r = i - which*72;
        float4 v = *(const float4*)(hn0 + (size_t)which*FF*HH + 4*r);
        float2* dst = &hs2[which][4*r];
        dst[0] = dup2(v.x); dst[1] = dup2(v.y);
        dst[2] = dup2(v.z); dst[3] = dup2(v.w);
    }
    if (t < 54) {                                // 54 float4 = 216 floats
        float4 v = *(const float4*)(Wo1 + 4*t);
        w12[4*t+0] = dup2(v.x); w12[4*t+1] = dup2(v.y);
        w12[4*t+2] = dup2(v.z); w12[4*t+3] = dup2(v.w);
    }
    __syncthreads();

    int d0 = u, d1 = u + 64, d2 = u + 128, d3 = u + 192;
    float2 wcA[HH], wcB[HH];
#pragma unroll
    for (int h = 0; h < HH; ++h) {
        wcA[h] = make_float2(Wc[h*DD + d0], Wc[h*DD + d1]);
        wcB[h] = make_float2(Wc[h*DD + d2], Wc[h*DD + d3]);
    }
    float2 bcA = make_float2(bc[d0], bc[d1]);
    float2 bcB = make_float2(bc[d2], bc[d3]);

    float2 accA[SFD], accB[SFD];
#pragma unroll
    for (int s = 0; s < SFD; ++s) { accA[s] = dup2(bo1[s]); accB[s] = dup2(bo1[s]); }

    const float2* hbase = &hs2[half][0];
#pragma unroll 4
    for (int f = 0; f < FF; ++f) {
        const float4* hp = (const float4*)&hbase[f*HH];   // 8 float2, 16B aligned
        float2 aA = bcA, aB = bcB;
#pragma unroll
        for (int j = 0; j < 4; ++j) {
            float4 hv = hp[j];
            float2 lo = *(const float2*)&hv.x;
            float2 hi = *(const float2*)&hv.z;
            aA = fma2(lo, wcA[2*j],   aA);
            aA = fma2(hi, wcA[2*j+1], aA);
            aB = fma2(lo, wcB[2*j],   aB);
            aB = fma2(hi, wcB[2*j+1], aB);
        }
        float2 latA = tanh2(aA), latB = tanh2(aB);
        const float4* wp = (const float4*)&w12[f*SFD];    // 6 float2, 16B aligned
#pragma unroll
        for (int j = 0; j < 3; ++j) {
            float4 wv = wp[j];
            float2 lo = *(const float2*)&wv.x;
            float2 hi = *(const float2*)&wv.z;
            accA[2*j]   = fma2(latA, lo, accA[2*j]);
            accA[2*j+1] = fma2(latA, hi, accA[2*j+1]);
            accB[2*j]   = fma2(latB, lo, accB[2*j]);
            accB[2*j+1] = fma2(latB, hi, accB[2*j+1]);
        }
    }

    float2 resA = make_float2(bo2[d0], bo2[d1]);
    float2 resB = make_float2(bo2[d2], bo2[d3]);
#pragma unroll
    for (int s = 0; s < SFD; ++s) {
        float2 w2 = dup2(Wo2[s]);
        resA = fma2(tanh2(accA[s]), w2, resA);
        resB = fma2(tanh2(accB[s]), w2, resB);
    }

    float* o = out + (size_t)bq*DD;
    o[d0] = resA.x; o[d1] = resA.y;
    o[d2] = resB.x; o[d3] = resB.y;
}

// ---------------------------------------------------------------------------
extern "C" void kernel_launch(void* const* d_in, const int* in_sizes, int n_in,
                              void* d_out, int out_size) {
    const float* query = (const float*)d_in[0];
    const float* key   = (const float*)d_in[1];
    const float* value = (const float*)d_in[2];
    const float* mask  = (const float*)d_in[3];
    const float* Wq    = (const float*)d_in[4];
    const float* Wk    = (const float*)d_in[5];
    const float* Wc    = (const float*)d_in[6];
    const float* bc    = (const float*)d_in[7];
    const float* Wo1   = (const float*)d_in[8];
    const float* bo1   = (const float*)d_in[9];
    const float* Wo2   = (const float*)d_in[10];
    const float* bo2   = (const float*)d_in[11];
    float* out = (float*)d_out;

    proj_kernel<<<dim3(NB*TQ/16, 2), 256>>>(query, key, Wq, Wk);
    fused_attn_kernel<<<dim3(NB, HH, 4), 128>>>(value, mask);
    epilogue_kernel<<<NB*TQ/2, 128>>>(Wc, bc, Wo1, bo1, Wo2, bo2, out);
}

// round 7
// speedup vs baseline: 1.0685x; 1.0685x over previous
#include <cuda_runtime.h>

#define NB 16
#define TQ 256
#define TK 256
#define DD 256
#define FF 36
#define HH 8
#define DK 32
#define SFD 6

// Scratch (allocation-free rule: __device__ globals)
__device__ float g_Q[NB*TQ*DD];        // [b][q][h*DK+j]
__device__ float g_K[NB*TK*DD];        // [b][k][h*DK+j]
__device__ float g_HN[NB*TQ*FF*HH];    // [b][q][f][h]

// ---------------------------------------------------------------------------
// Packed fp32x2 helpers (sm_103a: FFMA2 via PTX only)
// ---------------------------------------------------------------------------
__device__ __forceinline__ float2 fma2(float2 a, float2 b, float2 c) {
    float2 d;
    asm("fma.rn.f32x2 %0, %1, %2, %3;"
        : "=l"(reinterpret_cast<unsigned long long&>(d))
        : "l"(reinterpret_cast<unsigned long long&>(a)),
          "l"(reinterpret_cast<unsigned long long&>(b)),
          "l"(reinterpret_cast<unsigned long long&>(c)));
    return d;
}
__device__ __forceinline__ float2 dup2(float s) { return make_float2(s, s); }
__device__ __forceinline__ float2 tanh2(float2 a) {
    float2 r;
    asm("tanh.approx.f32 %0, %1;" : "=f"(r.x) : "f"(a.x));
    asm("tanh.approx.f32 %0, %1;" : "=f"(r.y) : "f"(a.y));
    return r;
}

// ---------------------------------------------------------------------------
// Kernel 1: head projections as register-tiled SGEMM.
// out[n, h*32+j] = sum_d x[n,d] * W[h,d,j]  ==  X(8192x256) @ Wbig(256x256),
// Wbig[d][h*32+j] = W[h][d][j].
// Tile 128x128, k-tile 16, 256 threads, 8x8 outputs/thread (acc as float2
// col-pairs -> 32 FFMA2 vs 6 LDS.128 per kk). A-tile duplicated for FFMA2.
// Global fills register-double-buffered.
// ---------------------------------------------------------------------------
#define PM 128
#define PN 128
#define PKT 16

__global__ void __launch_bounds__(256) proj_kernel(
        const float* __restrict__ query, const float* __restrict__ key,
        const float* __restrict__ Wq,    const float* __restrict__ Wk) {
    __shared__ __align__(16) float As[PKT][2*PM + 4];   // [kk][2n] duplicated rows
    __shared__ __align__(16) float Bs[PKT][PN + 4];     // [kk][c]

    int n0 = blockIdx.x * PM;
    int c0 = blockIdx.y * PN;
    int which = blockIdx.z;
    const float* x = which ? key : query;
    const float* W = which ? Wk : Wq;

    int t  = threadIdx.x;
    int tn = t & 15;          // col quad: c0 + 4tn (+64)
    int tm = t >> 4;          // row quad: n0 + 4tm (+64)

    // fill-index precompute
    int fa_n  = t >> 1;                 // A fill: 2 float4/thread
    int fa_c4 = (t & 1) * 8;            //   k offsets 0..7 / 8..15 (2 float4)
    int fb_kk = t >> 5;                 // B fill: kk row (0..7, +8)
    int fb_cq = (t & 31) * 4;           //   col quad
    int fb_h  = (c0 + fb_cq) >> 5;
    int fb_j  = (c0 + fb_cq) & 31;

    float2 acc[8][4];
#pragma unroll
    for (int r = 0; r < 8; ++r)
#pragma unroll
        for (int p = 0; p < 4; ++p) acc[r][p] = make_float2(0.f, 0.f);

    // ---- prefetch tile 0 into registers
    float4 pa0, pa1, pb0, pb1;
    {
        const float* xr = x + (size_t)(n0 + fa_n)*DD + fa_c4;
        pa0 = *(const float4*)(xr);
        pa1 = *(const float4*)(xr + 4);
        const float* wr = W + ((size_t)fb_h*DD + fb_kk)*DK + fb_j;
        pb0 = *(const float4*)(wr);
        pb1 = *(const float4*)(wr + 8*DK);
    }

#pragma unroll 1
    for (int kt = 0; kt < DD; kt += PKT) {
        // ---- store prefetched regs to smem
        {
            float* a0 = &As[fa_c4][2*fa_n];
            *(float2*)(&As[fa_c4+0][2*fa_n]) = dup2(pa0.x);
            *(float2*)(&As[fa_c4+1][2*fa_n]) = dup2(pa0.y);
            *(float2*)(&As[fa_c4+2][2*fa_n]) = dup2(pa0.z);
            *(float2*)(&As[fa_c4+3][2*fa_n]) = dup2(pa0.w);
            *(float2*)(&As[fa_c4+4][2*fa_n]) = dup2(pa1.x);
            *(float2*)(&As[fa_c4+5][2*fa_n]) = dup2(pa1.y);
            *(float2*)(&As[fa_c4+6][2*fa_n]) = dup2(pa1.z);
            *(float2*)(&As[fa_c4+7][2*fa_n]) = dup2(pa1.w);
            (void)a0;
            *(float4*)(&Bs[fb_kk  ][fb_cq]) = pb0;
            *(float4*)(&Bs[fb_kk+8][fb_cq]) = pb1;
        }
        __syncthreads();

        // ---- prefetch next tile (overlaps compute)
        if (kt + PKT < DD) {
            const float* xr = x + (size_t)(n0 + fa_n)*DD + kt + PKT + fa_c4;
            pa0 = *(const float4*)(xr);
            pa1 = *(const float4*)(xr + 4);
            const float* wr = W + ((size_t)fb_h*DD + kt + PKT + fb_kk)*DK + fb_j;
            pb0 = *(const float4*)(wr);
            pb1 = *(const float4*)(wr + 8*DK);
        }

        // ---- compute
#pragma unroll
        for (int kk = 0; kk < PKT; ++kk) {
            float2 a[8], bv[4];
            *(float4*)&a[0] = *(const float4*)&As[kk][8*tm];
            *(float4*)&a[2] = *(const float4*)&As[kk][8*tm + 4];
            *(float4*)&a[4] = *(const float4*)&As[kk][8*tm + 128];
            *(float4*)&a[6] = *(const float4*)&As[kk][8*tm + 132];
            *(float4*)&bv[0] = *(const float4*)&Bs[kk][4*tn];
            *(float4*)&bv[2] = *(const float4*)&Bs[kk][4*tn + 64];
#pragma unroll
            for (int r = 0; r < 8; ++r)
#pragma unroll
                for (int p = 0; p < 4; ++p)
                    acc[r][p] = fma2(a[r], bv[p], acc[r][p]);
        }
        __syncthreads();
    }

    // ---- write out: rows 4tm+rr (+64), col quads c0+4tn (+64)
    float* out = which ? g_K : g_Q;
#pragma unroll
    for (int r = 0; r < 8; ++r) {
        int n = n0 + 4*tm + (r >> 2)*64 + (r & 3);
        // acc row index: a[] order was rows {4tm..4tm+3, 4tm+64..4tm+67}
        float4 lo, hi;
        *(float2*)&lo.x = acc[r][0];   // cols 4tn, 4tn+1
        *(float2*)&lo.z = acc[r][1];   // cols 4tn+2, 4tn+3
        *(float2*)&hi.x = acc[r][2];   // cols 4tn+64, 4tn+65
        *(float2*)&hi.z = acc[r][3];
        *(float4*)(out + (size_t)n*DD + c0 + 4*tn)      = lo;
        *(float4*)(out + (size_t)n*DD + c0 + 4*tn + 64) = hi;
    }
}

// ---------------------------------------------------------------------------
// Kernel 2 (fused score+apply): per (b, h, qtile-64) block, loop k-tiles of 32.
// Phase A: E[kk][q] = exp(Q.K) into smem. Phase B: accumulate num/den.
// ---------------------------------------------------------------------------
__global__ void __launch_bounds__(128, 4) fused_attn_kernel(
        const float* __restrict__ value, const float* __restrict__ mask) {
    int b = blockIdx.x, h = blockIdx.y;
    int q0 = blockIdx.z * 64;
    int t = threadIdx.x;

    __shared__ __align__(16) float Qst[32][68];     // [j][q] transposed Q tile
    __shared__ __align__(16) float Ksd[32][66];     // [kk][2j] duplicated K tile
    __shared__ __align__(16) float Es[32][68];      // [kk][q]
    __shared__ __align__(16) float Cs[32][4][20];   // [kk][fg][(mv,m)x9 + pad]

    // Load Q tile transposed (once per block)
    for (int i = t; i < 64*32; i += 128) {
        int q = i >> 5, j = i & 31;
        Qst[j][q] = g_Q[(size_t)(b*TQ + q0 + q)*DD + h*DK + j];
    }

    // Phase B mapping
    int qg = t >> 2;            // q local = qg*2 + qq
    int fg = t & 3;             // f = fg*9 + i
    // Phase A mapping
    int kkA = t & 31;
    int qq4 = t >> 5;           // 16-q chunk

    float2 nd[2][9];
#pragma unroll
    for (int qq = 0; qq < 2; ++qq)
#pragma unroll
        for (int i = 0; i < 9; ++i) nd[qq][i] = make_float2(0.f, 0.f);

#pragma unroll 1
    for (int kt = 0; kt < TK; kt += 32) {
        __syncthreads();   // previous iteration's readers of Ksd/Cs done
        // K tile fill, duplicated for FFMA2: 32kk x 32j, 8 per thread
#pragma unroll
        for (int r = 0; r < 8; ++r) {
            int i = t + r*128;
            int kk = i >> 5, j = i & 31;
            float kv = g_K[(size_t)(b*TK + kt + kk)*DD + h*DK + j];
            *(float2*)&Ksd[kk][2*j] = make_float2(kv, kv);
        }
        // Cs fill: 32k x 9 float4-groups over f
        for (int i = t; i < 288; i += 128) {
            int k = i / 9;
            int c4 = (i - k*9) * 4;
            size_t base = (size_t)(b*TK + kt + k)*FF + c4;
            float4 mm = *(const float4*)(mask + base);
            float4 vv = *(const float4*)(value + base);
#pragma unroll
            for (int u = 0; u < 4; ++u) {
                int f = c4 + u;
                int g = f / 9, ii = f - g*9;
                float m = (&mm.x)[u], v = (&vv.x)[u];
                Cs[k][g][2*ii]   = m * v;
                Cs[k][g][2*ii+1] = m;
            }
        }
        __syncthreads();

        // ---- Phase A: thread owns kk = kkA, computes 16 q's (qq4*16..+15)
        {
            float2 acc2[8];
#pragma unroll
            for (int p = 0; p < 8; ++p) acc2[p] = make_float2(0.f, 0.f);
#pragma unroll
            for (int jc = 0; jc < 4; ++jc) {      // 8 j at a time (reg-lean)
                float2 kr2[8];
#pragma unroll
                for (int j = 0; j < 8; ++j)
                    kr2[j] = *(const float2*)&Ksd[kkA][2*(jc*8 + j)];
#pragma unroll
                for (int j = 0; j < 8; ++j) {
                    const float4* qp = (const float4*)&Qst[jc*8 + j][qq4*16];
#pragma unroll
                    for (int c = 0; c < 4; ++c) {
                        float4 qv = qp[c];
                        acc2[2*c]   = fma2(*(const float2*)&qv.x, kr2[j], acc2[2*c]);
                        acc2[2*c+1] = fma2(*(const float2*)&qv.z, kr2[j], acc2[2*c+1]);
                    }
                }
            }
#pragma unroll
            for (int c = 0; c < 4; ++c) {
                float4 ev;
                ev.x = __expf(fminf(acc2[2*c].x,   80.f));
                ev.y = __expf(fminf(acc2[2*c].y,   80.f));
                ev.z = __expf(fminf(acc2[2*c+1].x, 80.f));
                ev.w = __expf(fminf(acc2[2*c+1].y, 80.f));
                *(float4*)&Es[kkA][qq4*16 + 4*c] = ev;
            }
        }
        __syncthreads();

        // ---- Phase B: accumulate num/den (no temp arrays)
#pragma unroll 4
        for (int kk = 0; kk < 32; ++kk) {
            float2 e2 = *(const float2*)&Es[kk][qg*2];
            float2 e0 = dup2(e2.x), e1 = dup2(e2.y);
            const float4* cp = (const float4*)&Cs[kk][fg][0];
            float4 c0 = cp[0], c1 = cp[1], c2 = cp[2], c3 = cp[3], c4v = cp[4];
            nd[0][0] = fma2(e0, *(const float2*)&c0.x,  nd[0][0]);
            nd[1][0] = fma2(e1, *(const float2*)&c0.x,  nd[1][0]);
            nd[0][1] = fma2(e0, *(const float2*)&c0.z,  nd[0][1]);
            nd[1][1] = fma2(e1, *(const float2*)&c0.z,  nd[1][1]);
            nd[0][2] = fma2(e0, *(const float2*)&c1.x,  nd[0][2]);
            nd[1][2] = fma2(e1, *(const float2*)&c1.x,  nd[1][2]);
            nd[0][3] = fma2(e0, *(const float2*)&c1.z,  nd[0][3]);
            nd[1][3] = fma2(e1, *(const float2*)&c1.z,  nd[1][3]);
            nd[0][4] = fma2(e0, *(const float2*)&c2.x,  nd[0][4]);
            nd[1][4] = fma2(e1, *(const float2*)&c2.x,  nd[1][4]);
            nd[0][5] = fma2(e0, *(const float2*)&c2.z,  nd[0][5]);
            nd[1][5] = fma2(e1, *(const float2*)&c2.z,  nd[1][5]);
            nd[0][6] = fma2(e0, *(const float2*)&c3.x,  nd[0][6]);
            nd[1][6] = fma2(e1, *(const float2*)&c3.x,  nd[1][6]);
            nd[0][7] = fma2(e0, *(const float2*)&c3.z,  nd[0][7]);
            nd[1][7] = fma2(e1, *(const float2*)&c3.z,  nd[1][7]);
            nd[0][8] = fma2(e0, *(const float2*)&c4v.x, nd[0][8]);
            nd[1][8] = fma2(e1, *(const float2*)&c4v.x, nd[1][8]);
        }
    }

#pragma unroll
    for (int qq = 0; qq < 2; ++qq) {
        int q = q0 + qg*2 + qq;
        float* o = g_HN + (size_t)(b*TQ + q)*FF*HH + h;
#pragma unroll
        for (int i = 0; i < 9; ++i) {
            int f = fg*9 + i;
            o[(size_t)f*HH] = __fdividef(nd[qq][i].x, nd[qq][i].y);
        }
    }
}

// ---------------------------------------------------------------------------
// Kernel 3: fused epilogue. Block = 2 (b,q) rows; 64 threads per row; thread
// owns 4 d's = two FFMA2 pairs.
// ---------------------------------------------------------------------------
__global__ void __launch_bounds__(128) epilogue_kernel(
        const float* __restrict__ Wc,  const float* __restrict__ bc,
        const float* __restrict__ Wo1, const float* __restrict__ bo1,
        const float* __restrict__ Wo2, const float* __restrict__ bo2,
        float* __restrict__ out) {
    int t    = threadIdx.x;
    int half = t >> 6;           // which bq of the pair
    int u    = t & 63;           // d base
    int bq   = 2*blockIdx.x + half;

    __shared__ __align__(16) float2 hs2[2][FF*HH];   // duplicated pairs, per bq
    __shared__ __align__(16) float2 w12[FF*SFD];

    const float* hn0 = g_HN + (size_t)(2*blockIdx.x)*FF*HH;
    for (int i = t; i < 144; i += 128) {        // 2 x 72 float4
        int which = i / 72, r = i - which*72;
        float4 v = *(const float4*)(hn0 + (size_t)which*FF*HH + 4*r);
        float2* dst = &hs2[which][4*r];
        dst[0] = dup2(v.x); dst[1] = dup2(v.y);
        dst[2] = dup2(v.z); dst[3] = dup2(v.w);
    }
    if (t < 54) {                                // 54 float4 = 216 floats
        float4 v = *(const float4*)(Wo1 + 4*t);
        w12[4*t+0] = dup2(v.x); w12[4*t+1] = dup2(v.y);
        w12[4*t+2] = dup2(v.z); w12[4*t+3] = dup2(v.w);
    }
    __syncthreads();

    int d0 = u, d1 = u + 64, d2 = u + 128, d3 = u + 192;
    float2 wcA[HH], wcB[HH];
#pragma unroll
    for (int h = 0; h < HH; ++h) {
        wcA[h] = make_float2(Wc[h*DD + d0], Wc[h*DD + d1]);
        wcB[h] = make_float2(Wc[h*DD + d2], Wc[h*DD + d3]);
    }
    float2 bcA = make_float2(bc[d0], bc[d1]);
    float2 bcB = make_float2(bc[d2], bc[d3]);

    float2 accA[SFD], accB[SFD];
#pragma unroll
    for (int s = 0; s < SFD; ++s) { accA[s] = dup2(bo1[s]); accB[s] = dup2(bo1[s]); }

    const float2* hbase = &hs2[half][0];
#pragma unroll 4
    for (int f = 0; f < FF; ++f) {
        const float4* hp = (const float4*)&hbase[f*HH];   // 8 float2, 16B aligned
        float2 aA = bcA, aB = bcB;
#pragma unroll
        for (int j = 0; j < 4; ++j) {
            float4 hv = hp[j];
            float2 lo = *(const float2*)&hv.x;
            float2 hi = *(const float2*)&hv.z;
            aA = fma2(lo, wcA[2*j],   aA);
            aA = fma2(hi, wcA[2*j+1], aA);
            aB = fma2(lo, wcB[2*j],   aB);
            aB = fma2(hi, wcB[2*j+1], aB);
        }
        float2 latA = tanh2(aA), latB = tanh2(aB);
        const float4* wp = (const float4*)&w12[f*SFD];    // 6 float2, 16B aligned
#pragma unroll
        for (int j = 0; j < 3; ++j) {
            float4 wv = wp[j];
            float2 lo = *(const float2*)&wv.x;
            float2 hi = *(const float2*)&wv.z;
            accA[2*j]   = fma2(latA, lo, accA[2*j]);
            accA[2*j+1] = fma2(latA, hi, accA[2*j+1]);
            accB[2*j]   = fma2(latB, lo, accB[2*j]);
            accB[2*j+1] = fma2(latB, hi, accB[2*j+1]);
        }
    }

    float2 resA = make_float2(bo2[d0], bo2[d1]);
    float2 resB = make_float2(bo2[d2], bo2[d3]);
#pragma unroll
    for (int s = 0; s < SFD; ++s) {
        float2 w2 = dup2(Wo2[s]);
        resA = fma2(tanh2(accA[s]), w2, resA);
        resB = fma2(tanh2(accB[s]), w2, resB);
    }

    float* o = out + (size_t)bq*DD;
    o[d0] = resA.x; o[d1] = resA.y;
    o[d2] = resB.x; o[d3] = resB.y;
}

// ---------------------------------------------------------------------------
extern "C" void kernel_launch(void* const* d_in, const int* in_sizes, int n_in,
                              void* d_out, int out_size) {
    const float* query = (const float*)d_in[0];
    const float* key   = (const float*)d_in[1];
    const float* value = (const float*)d_in[2];
    const float* mask  = (const float*)d_in[3];
    const float* Wq    = (const float*)d_in[4];
    const float* Wk    = (const float*)d_in[5];
    const float* Wc    = (const float*)d_in[6];
    const float* bc    = (const float*)d_in[7];
    const float* Wo1   = (const float*)d_in[8];
    const float* bo1   = (const float*)d_in[9];
    const float* Wo2   = (const float*)d_in[10];
    const float* bo2   = (const float*)d_in[11];
    float* out = (float*)d_out;

    proj_kernel<<<dim3(NB*TQ/PM, DD/PN, 2), 256>>>(query, key, Wq, Wk);
    fused_attn_kernel<<<dim3(NB, HH, 4), 128>>>(value, mask);
    epilogue_kernel<<<NB*TQ/2, 128>>>(Wc, bc, Wo1, bo1, Wo2, bo2, out);
}